// round 12
// baseline (speedup 1.0000x reference)
#include <cuda_runtime.h>

#define NPG    1430
#define GENE0  1421
#define NHEADS 9

static const int MAXN = 732160;            // 1430 * 512 nodes
static const int MAXA = 512 * NHEADS * 16; // agg2 accumulator
static const int GCAP = 262144;            // gene-edge list capacity (~37K expected)
static const int BMW  = MAXN / 32;         // bitmap words (22880 -> 91.5KB)

// Scratch (allocation-free: __device__ globals; zero-initialized at load).
// Self-cleaning invariant: every kernel_launch leaves degi/bm/gcount zeroed
// (by k_node1 / k_l2 / k_final respectively), so no upfront zero pass.
// dinv/u (gather targets) and raw (RED target) are SEPARATE arrays so the
// scatter's L1-cached gathers and its L2 atomics never share cache lines.
__device__ int      g_degi[MAXN];
__device__ float    g_dinv[MAXN];
__device__ float    g_u[MAXN];       // dinv[n] * x[n]
__device__ float    g_raw[MAXN];     // sum over in-edges of u[src] (valid at S only)
__device__ float    g_agg2[MAXA];    // layer-2 raw aggregation at gene nodes
__device__ int2     g_glist2[GCAP];  // resolved gene edges: {src node, agg2 base}
__device__ int      g_gcount;
__device__ unsigned g_bm[BMW];       // bitmap: S = {gene-edge srcs} U {gene dsts}

// ---------------------------------------------------------------------------
// Pass 1: in-degree count + gene-edge RESOLUTION + S-membership bitmap.
// Gene-dst detection is pure arithmetic (v % 1430 >= 1421). For each gene
// edge (~0.63%): store the resolved pair {src, agg2_base}, set bitmap bits
// for src and dst. Reservation is block-aggregated.
// ---------------------------------------------------------------------------
__global__ void k_deg(const int* __restrict__ src, const int* __restrict__ dst,
                      int e4) {
    __shared__ int s_cnt, s_base;
    if (threadIdx.x == 0) s_cnt = 0;
    __syncthreads();

    int i = blockIdx.x * blockDim.x + threadIdx.x;
    int2 hits[4];
    int c = 0;
    if (i < e4) {
        int4 d = __ldcs((const int4*)dst + i);
        int dd[4] = {d.x, d.y, d.z, d.w};
#pragma unroll
        for (int j = 0; j < 4; j++) {
            unsigned v = (unsigned)dd[j];
            atomicAdd(&g_degi[v], 1);
            unsigned q = v / (unsigned)NPG;
            unsigned r = v - q * (unsigned)NPG;
            if (r >= (unsigned)GENE0) {
                int e = i * 4 + j;
                unsigned s = (unsigned)__ldg(src + e);
                int gi = ((int)q * NHEADS + (int)(r - (unsigned)GENE0)) * 16;
                hits[c++] = make_int2((int)s, gi);
                atomicOr(&g_bm[s >> 5], 1u << (s & 31u));   // src needs t
                atomicOr(&g_bm[v >> 5], 1u << (v & 31u));   // gene dst needs raw
            }
        }
    }

    int my_off = 0;
    if (c) my_off = atomicAdd(&s_cnt, c);
    __syncthreads();
    if (threadIdx.x == 0) s_base = s_cnt ? atomicAdd(&g_gcount, s_cnt) : 0;
    __syncthreads();

    int base = s_base + my_off;
    for (int k = 0; k < c; k++) {
        int p = base + k;
        if (p < GCAP) g_glist2[p] = hits[k];
    }
}

// ---------------------------------------------------------------------------
// Per-node: dinv = rsqrt(deg+1), u = dinv * x.  Zeroes raw and agg2 and
// self-cleans degi (k_node1 is degi's only consumer).
// ---------------------------------------------------------------------------
__global__ void k_node1(const float* __restrict__ x, int n4, int a4) {
    int i = blockIdx.x * blockDim.x + threadIdx.x;
    if (i < a4) ((float4*)g_agg2)[i] = make_float4(0.f, 0.f, 0.f, 0.f);
    if (i >= n4) return;
    int4   dg = ((const int4*)g_degi)[i];
    float4 xv = __ldg((const float4*)x + i);
    float4 dv, uv;
    dv.x = rsqrtf((float)dg.x + 1.0f); uv.x = dv.x * xv.x;
    dv.y = rsqrtf((float)dg.y + 1.0f); uv.y = dv.y * xv.y;
    dv.z = rsqrtf((float)dg.z + 1.0f); uv.z = dv.z * xv.z;
    dv.w = rsqrtf((float)dg.w + 1.0f); uv.w = dv.w * xv.w;
    ((float4*)g_dinv)[i] = dv;
    ((float4*)g_u)[i]    = uv;
    ((float4*)g_raw)[i]  = make_float4(0.f, 0.f, 0.f, 0.f);
    ((int4*)g_degi)[i]   = make_int4(0, 0, 0, 0);     // self-clean for next replay
}

// ---------------------------------------------------------------------------
// Pass 2 (sparsified, SMEM bitmap): raw[dst] += u[src] ONLY when dst is in S.
// The 91.5KB membership bitmap is copied into dynamic shared memory per block;
// the per-edge random test becomes an LDS (~4-5 cyc/warp for 32 random words)
// instead of 32 L1tex wavefronts/warp. Grid-stride; 2 blocks/SM.
// ---------------------------------------------------------------------------
__global__ void k_scatter(const int* __restrict__ src, const int* __restrict__ dst,
                          int e4) {
    extern __shared__ unsigned s_bm[];
    for (int i = threadIdx.x; i < BMW; i += blockDim.x)
        s_bm[i] = g_bm[i];
    __syncthreads();

    int stride = gridDim.x * blockDim.x;
    for (int i = blockIdx.x * blockDim.x + threadIdx.x; i < e4; i += stride) {
        int4 d4 = __ldcs((const int4*)dst + i);
        int dd[4] = {d4.x, d4.y, d4.z, d4.w};
#pragma unroll
        for (int j = 0; j < 4; j++) {
            unsigned v = (unsigned)dd[j];
            unsigned w = s_bm[v >> 5];
            if ((w >> (v & 31u)) & 1u) {
                unsigned s = (unsigned)__ldg(src + i * 4 + j);
                atomicAdd(&g_raw[v], __ldg(&g_u[s]));
            }
        }
    }
}

// ---------------------------------------------------------------------------
// Pass 3: layer-2 scatter over RESOLVED gene edges.
// 16 lanes per edge; lane c computes channel c and issues ONE atomic (16
// lane-atomics coalesce into one 64B-line wavefront per edge). Chain:
// glist2[g] (sequential) -> 3 PARALLEL random loads -> agg2 atomic.
// Also zeroes the bitmap (its reader k_scatter has completed).
// ---------------------------------------------------------------------------
__global__ void k_l2(const float* __restrict__ W1, const float* __restrict__ b1,
                     const float* __restrict__ W2) {
    __shared__ float sW1[16], sb1[16], sW2[256];
    int tid = threadIdx.x;
    if (tid < 16) { sW1[tid] = W1[tid]; sb1[tid] = b1[tid]; }
    for (int j = tid; j < 256; j += blockDim.x) sW2[j] = W2[j];
    __syncthreads();

    int flat = blockIdx.x * blockDim.x + tid;
    if (flat < BMW) g_bm[flat] = 0u;           // self-clean for next replay

    int cnt = g_gcount;
    if (cnt > GCAP) cnt = GCAP;

    int lane    = tid & 15;
    int group   = flat >> 4;
    int gstride = (gridDim.x * blockDim.x) >> 4;

    for (int g = group; g < cnt; g += gstride) {
        int2 sd = __ldg(&g_glist2[g]);         // {src node, agg2 base}
        float ws = __ldg(&g_dinv[sd.x]);       // 3 independent random loads,
        float rs = __ldg(&g_raw[sd.x]);        // issued concurrently
        float us = __ldg(&g_u[sd.x]);
        float ts = ws * (rs + us);             // t inline

        float m = 0.f;
#pragma unroll
        for (int k = 0; k < 16; k++) {
            float h = fmaxf(fmaf(ts, sW1[k], sb1[k]), 0.f);
            m = fmaf(h, sW2[k * 16 + lane], m);
        }

        atomicAdd(&g_agg2[sd.y + lane], ws * m);
    }
}

// ---------------------------------------------------------------------------
// Final: per gene node, close layer 2 (self loop + scale + b2 + relu),
// then the per-head MLP.  Also zeroes gcount (reader k_l2 has completed).
// ---------------------------------------------------------------------------
__global__ void k_final(const float* __restrict__ W1, const float* __restrict__ b1,
                        const float* __restrict__ W2, const float* __restrict__ b2,
                        const float* __restrict__ fw1, const float* __restrict__ fb1,
                        const float* __restrict__ fw2, const float* __restrict__ fb2,
                        float* __restrict__ out, int G) {
    int tid = blockIdx.x * blockDim.x + threadIdx.x;
    if (tid == 0) g_gcount = 0;                // self-clean for next replay
    if (tid >= G * NHEADS) return;
    int head = tid / G;
    int g    = tid - head * G;
    int node = g * NPG + GENE0 + head;

    float dv = g_dinv[node];
    float tn = dv * (g_raw[node] + g_u[node]); // t inline

    float m[16];
#pragma unroll
    for (int c = 0; c < 16; c++) m[c] = 0.f;
#pragma unroll
    for (int k = 0; k < 16; k++) {
        float h = fmaxf(fmaf(tn, __ldg(W1 + k), __ldg(b1 + k)), 0.f);
#pragma unroll
        for (int c = 0; c < 16; c++) m[c] = fmaf(h, __ldg(W2 + k * 16 + c), m[c]);
    }

    int gi = (g * NHEADS + head) * 16;
    float h2[16];
#pragma unroll
    for (int c = 0; c < 16; c++) {
        float a = dv * (g_agg2[gi + c] + dv * m[c]) + __ldg(b2 + c);
        h2[c] = fmaxf(a, 0.f);
    }

    float pred = __ldg(fb2 + head);
#pragma unroll
    for (int j = 0; j < 8; j++) {
        float z = __ldg(fb1 + head * 8 + j);
#pragma unroll
        for (int c = 0; c < 16; c++)
            z = fmaf(h2[c], __ldg(fw1 + head * 128 + c * 8 + j), z);
        z = fmaxf(z, 0.f);
        pred = fmaf(z, __ldg(fw2 + head * 8 + j), pred);
    }
    out[head * G + g] = pred;
}

// ---------------------------------------------------------------------------
extern "C" void kernel_launch(void* const* d_in, const int* in_sizes, int n_in,
                              void* d_out, int out_size) {
    const float* x   = (const float*)d_in[0];
    const int*   ei  = (const int*)  d_in[1];
    const float* W1  = (const float*)d_in[3];
    const float* b1  = (const float*)d_in[4];
    const float* W2  = (const float*)d_in[5];
    const float* b2  = (const float*)d_in[6];
    const float* fw1 = (const float*)d_in[7];
    const float* fb1 = (const float*)d_in[8];
    const float* fw2 = (const float*)d_in[9];
    const float* fb2 = (const float*)d_in[10];
    float* out = (float*)d_out;

    int N = in_sizes[0];             // x is [N,1]   (732160, div by 4)
    int E = in_sizes[1] / 2;         // edge_index is [2,E]  (E div by 4)
    int G = in_sizes[2] / NHEADS;    // y is [G*9]

    const int* src = ei;
    const int* dst = ei + E;

    int n4 = N / 4;
    int e4 = E / 4;
    int a4 = (G * NHEADS * 16) / 4;

    const int B = 256;
    const int SMEM_BM = BMW * (int)sizeof(unsigned);   // 91520 bytes

    // Opt-in to >48KB dynamic smem (idempotent; host-side attribute, not a
    // stream op, so it does not break graph capture).
    static int smem_set = 0;
    if (!smem_set) {
        cudaFuncSetAttribute(k_scatter, cudaFuncAttributeMaxDynamicSharedMemorySize,
                             SMEM_BM);
        smem_set = 1;
    }

    k_deg<<<(e4 + B - 1) / B, B>>>(src, dst, e4);
    k_node1<<<(n4 + B - 1) / B, B>>>(x, n4, a4);
    k_scatter<<<296, 512, SMEM_BM>>>(src, dst, e4);   // 2 blocks/SM, smem bitmap
    k_l2<<<2560, B>>>(W1, b1, W2);                    // 40960 groups >= expected cnt
    k_final<<<(G * NHEADS + 31) / 32, 32>>>(W1, b1, W2, b2, fw1, fb1, fw2, fb2, out, G);
}

// round 14
// speedup vs baseline: 1.0835x; 1.0835x over previous
#include <cuda_runtime.h>

#define NPG    1430
#define GENE0  1421
#define NHEADS 9

static const int MAXN = 732160;            // 1430 * 512 nodes
static const int MAXA = 512 * NHEADS * 16; // agg2 accumulator
static const int GCAP = 262144;            // gene-edge list capacity (~37K expected)
static const int BMW  = MAXN / 32;         // bitmap words (22880 -> 91.5KB, L1-resident)

// Scratch (allocation-free: __device__ globals; zero-initialized at load).
// Self-cleaning invariant: every kernel_launch leaves degi/bm/gcount zeroed
// (by k_node1 / k_l2 / k_final respectively), so no upfront zero pass.
// dinv/u (gather targets) and raw (RED target) are SEPARATE arrays so the
// scatter's L1-cached gathers and its L2 atomics never share cache lines.
__device__ int      g_degi[MAXN];
__device__ float    g_dinv[MAXN];
__device__ float    g_u[MAXN];       // dinv[n] * x[n]
__device__ float    g_raw[MAXN];     // sum over in-edges of u[src] (valid at S only)
__device__ float    g_agg2[MAXA];    // layer-2 raw aggregation at gene nodes
__device__ int2     g_glist2[GCAP];  // resolved gene edges: {src node, agg2 base}
__device__ int      g_gcount;
__device__ unsigned g_bm[BMW];       // bitmap: S = {gene-edge srcs} U {gene dsts}

// ---------------------------------------------------------------------------
// Pass 1: in-degree count + gene-edge RESOLUTION + S-membership bitmap.
// Gene-dst detection is pure arithmetic (v % 1430 >= 1421). For each gene
// edge (~0.63%): store the resolved pair {src, agg2_base}, set bitmap bits
// for src and dst. Reservation is block-aggregated (one global atomic/block).
// ---------------------------------------------------------------------------
__global__ void k_deg(const int* __restrict__ src, const int* __restrict__ dst,
                      int e4) {
    __shared__ int s_cnt, s_base;
    if (threadIdx.x == 0) s_cnt = 0;
    __syncthreads();

    int i = blockIdx.x * blockDim.x + threadIdx.x;
    int2 hits[4];
    int c = 0;
    if (i < e4) {
        int4 d = __ldcs((const int4*)dst + i);
        int dd[4] = {d.x, d.y, d.z, d.w};
#pragma unroll
        for (int j = 0; j < 4; j++) {
            unsigned v = (unsigned)dd[j];
            atomicAdd(&g_degi[v], 1);
            unsigned q = v / (unsigned)NPG;
            unsigned r = v - q * (unsigned)NPG;
            if (r >= (unsigned)GENE0) {
                int e = i * 4 + j;
                unsigned s = (unsigned)__ldg(src + e);
                int gi = ((int)q * NHEADS + (int)(r - (unsigned)GENE0)) * 16;
                hits[c++] = make_int2((int)s, gi);
                atomicOr(&g_bm[s >> 5], 1u << (s & 31u));   // src needs t
                atomicOr(&g_bm[v >> 5], 1u << (v & 31u));   // gene dst needs raw
            }
        }
    }

    int my_off = 0;
    if (c) my_off = atomicAdd(&s_cnt, c);
    __syncthreads();
    if (threadIdx.x == 0) s_base = s_cnt ? atomicAdd(&g_gcount, s_cnt) : 0;
    __syncthreads();

    int base = s_base + my_off;
    for (int k = 0; k < c; k++) {
        int p = base + k;
        if (p < GCAP) g_glist2[p] = hits[k];
    }
}

// ---------------------------------------------------------------------------
// Per-node: dinv = rsqrt(deg+1), u = dinv * x.  Zeroes raw and agg2 and
// self-cleans degi (k_node1 is degi's only consumer).
// ---------------------------------------------------------------------------
__global__ void k_node1(const float* __restrict__ x, int n4, int a4) {
    int i = blockIdx.x * blockDim.x + threadIdx.x;
    if (i < a4) ((float4*)g_agg2)[i] = make_float4(0.f, 0.f, 0.f, 0.f);
    if (i >= n4) return;
    int4   dg = ((const int4*)g_degi)[i];
    float4 xv = __ldg((const float4*)x + i);
    float4 dv, uv;
    dv.x = rsqrtf((float)dg.x + 1.0f); uv.x = dv.x * xv.x;
    dv.y = rsqrtf((float)dg.y + 1.0f); uv.y = dv.y * xv.y;
    dv.z = rsqrtf((float)dg.z + 1.0f); uv.z = dv.z * xv.z;
    dv.w = rsqrtf((float)dg.w + 1.0f); uv.w = dv.w * xv.w;
    ((float4*)g_dinv)[i] = dv;
    ((float4*)g_u)[i]    = uv;
    ((float4*)g_raw)[i]  = make_float4(0.f, 0.f, 0.f, 0.f);
    ((int4*)g_degi)[i]   = make_int4(0, 0, 0, 0);     // self-clean for next replay
}

// ---------------------------------------------------------------------------
// Pass 2 (sparsified): raw[dst] += u[src] ONLY when dst is in S (~5.6% of
// edges). One random access per edge (bitmap word; 91.5KB bitmap stays
// L1-resident). src is loaded SCALAR and only on a hit. (R9 configuration —
// measured best; the SMEM-bitmap variant lost to occupancy/L1-carveout.)
// ---------------------------------------------------------------------------
__global__ void k_scatter(const int* __restrict__ src, const int* __restrict__ dst,
                          int e4) {
    int i = blockIdx.x * blockDim.x + threadIdx.x;
    if (i >= e4) return;
    int4 d4 = __ldcs((const int4*)dst + i);
    int dd[4] = {d4.x, d4.y, d4.z, d4.w};
#pragma unroll
    for (int j = 0; j < 4; j++) {
        unsigned v = (unsigned)dd[j];
        unsigned w = __ldg(&g_bm[v >> 5]);
        if ((w >> (v & 31u)) & 1u) {
            unsigned s = (unsigned)__ldg(src + i * 4 + j);
            atomicAdd(&g_raw[v], __ldg(&g_u[s]));
        }
    }
}

// ---------------------------------------------------------------------------
// Pass 3: layer-2 scatter over RESOLVED gene edges.
// 16 lanes per edge; lane c computes channel c and issues ONE atomic (16
// lane-atomics coalesce into one 64B-line wavefront per edge). Chain:
// glist2[g] (sequential) -> 3 PARALLEL random loads -> agg2 atomic.
// Also zeroes the bitmap (its reader k_scatter has completed).
// ---------------------------------------------------------------------------
__global__ void k_l2(const float* __restrict__ W1, const float* __restrict__ b1,
                     const float* __restrict__ W2) {
    __shared__ float sW1[16], sb1[16], sW2[256];
    int tid = threadIdx.x;
    if (tid < 16) { sW1[tid] = W1[tid]; sb1[tid] = b1[tid]; }
    for (int j = tid; j < 256; j += blockDim.x) sW2[j] = W2[j];
    __syncthreads();

    int flat = blockIdx.x * blockDim.x + tid;
    if (flat < BMW) g_bm[flat] = 0u;           // self-clean for next replay

    int cnt = g_gcount;
    if (cnt > GCAP) cnt = GCAP;

    int lane    = tid & 15;
    int group   = flat >> 4;
    int gstride = (gridDim.x * blockDim.x) >> 4;

    for (int g = group; g < cnt; g += gstride) {
        int2 sd = __ldg(&g_glist2[g]);         // {src node, agg2 base}
        float ws = __ldg(&g_dinv[sd.x]);       // 3 independent random loads,
        float rs = __ldg(&g_raw[sd.x]);        // issued concurrently
        float us = __ldg(&g_u[sd.x]);
        float ts = ws * (rs + us);             // t inline

        float m = 0.f;
#pragma unroll
        for (int k = 0; k < 16; k++) {
            float h = fmaxf(fmaf(ts, sW1[k], sb1[k]), 0.f);
            m = fmaf(h, sW2[k * 16 + lane], m);
        }

        atomicAdd(&g_agg2[sd.y + lane], ws * m);
    }
}

// ---------------------------------------------------------------------------
// Final: per gene node, close layer 2 (self loop + scale + b2 + relu),
// then the per-head MLP.  Also zeroes gcount (reader k_l2 has completed).
// ---------------------------------------------------------------------------
__global__ void k_final(const float* __restrict__ W1, const float* __restrict__ b1,
                        const float* __restrict__ W2, const float* __restrict__ b2,
                        const float* __restrict__ fw1, const float* __restrict__ fb1,
                        const float* __restrict__ fw2, const float* __restrict__ fb2,
                        float* __restrict__ out, int G) {
    int tid = blockIdx.x * blockDim.x + threadIdx.x;
    if (tid == 0) g_gcount = 0;                // self-clean for next replay
    if (tid >= G * NHEADS) return;
    int head = tid / G;
    int g    = tid - head * G;
    int node = g * NPG + GENE0 + head;

    float dv = g_dinv[node];
    float tn = dv * (g_raw[node] + g_u[node]); // t inline

    float m[16];
#pragma unroll
    for (int c = 0; c < 16; c++) m[c] = 0.f;
#pragma unroll
    for (int k = 0; k < 16; k++) {
        float h = fmaxf(fmaf(tn, __ldg(W1 + k), __ldg(b1 + k)), 0.f);
#pragma unroll
        for (int c = 0; c < 16; c++) m[c] = fmaf(h, __ldg(W2 + k * 16 + c), m[c]);
    }

    int gi = (g * NHEADS + head) * 16;
    float h2[16];
#pragma unroll
    for (int c = 0; c < 16; c++) {
        float a = dv * (g_agg2[gi + c] + dv * m[c]) + __ldg(b2 + c);
        h2[c] = fmaxf(a, 0.f);
    }

    float pred = __ldg(fb2 + head);
#pragma unroll
    for (int j = 0; j < 8; j++) {
        float z = __ldg(fb1 + head * 8 + j);
#pragma unroll
        for (int c = 0; c < 16; c++)
            z = fmaf(h2[c], __ldg(fw1 + head * 128 + c * 8 + j), z);
        z = fmaxf(z, 0.f);
        pred = fmaf(z, __ldg(fw2 + head * 8 + j), pred);
    }
    out[head * G + g] = pred;
}

// ---------------------------------------------------------------------------
extern "C" void kernel_launch(void* const* d_in, const int* in_sizes, int n_in,
                              void* d_out, int out_size) {
    const float* x   = (const float*)d_in[0];
    const int*   ei  = (const int*)  d_in[1];
    const float* W1  = (const float*)d_in[3];
    const float* b1  = (const float*)d_in[4];
    const float* W2  = (const float*)d_in[5];
    const float* b2  = (const float*)d_in[6];
    const float* fw1 = (const float*)d_in[7];
    const float* fb1 = (const float*)d_in[8];
    const float* fw2 = (const float*)d_in[9];
    const float* fb2 = (const float*)d_in[10];
    float* out = (float*)d_out;

    int N = in_sizes[0];             // x is [N,1]   (732160, div by 4)
    int E = in_sizes[1] / 2;         // edge_index is [2,E]  (E div by 4)
    int G = in_sizes[2] / NHEADS;    // y is [G*9]

    const int* src = ei;
    const int* dst = ei + E;

    int n4 = N / 4;
    int e4 = E / 4;
    int a4 = (G * NHEADS * 16) / 4;

    const int B = 256;

    k_deg<<<(e4 + B - 1) / B, B>>>(src, dst, e4);
    k_node1<<<(n4 + B - 1) / B, B>>>(x, n4, a4);
    k_scatter<<<(e4 + B - 1) / B, B>>>(src, dst, e4);
    k_l2<<<2560, B>>>(W1, b1, W2);               // 40960 groups >= expected cnt
    k_final<<<(G * NHEADS + 31) / 32, 32>>>(W1, b1, W2, b2, fw1, fb1, fw2, fb2, out, G);
}